// round 13
// baseline (speedup 1.0000x reference)
#include <cuda_runtime.h>

typedef unsigned long long u64;

#define NXg 256
#define NYg 256
#define NCELL (NXg*NYg)
#define TSTEPS 256
#define NSIG 2
#define TR 32            // tile rows (x)
#define TC 16            // tile cols (y)
#define EPP 32           // smem pitch: 4 left guard + 24 + 4 right guard (16B aligned cols)
#define SROWS 42         // 1 top guard + 40 + 1 bottom guard
#define ROW0 1
#define COL0 4
#define NTH 128
#define NBLK 120         // 20 rows x 6 cols of 2x4-cell blocks (ext tile 40x24)
#define BPR 6
#define TILES_X 8
#define TILES_Y 16
#define NBS (TILES_X*TILES_Y)   // 128 CTAs per signal
#define NB (NSIG*NBS)           // 256 CTAs total

// Ping-pong magnetization state (only interior band cells ever written/read)
__device__ __align__(16) float g_state[2][NSIG][3*NCELL];
// per-tile monotonic step flags, one 32B sector each (zero-init; monotonic across replays)
__device__ unsigned g_done[NB*8];

// ---- packed f32x2 helpers ----
static __device__ __forceinline__ u64 pk2(float lo, float hi) {
    u64 r; asm("mov.b64 %0,{%1,%2};" : "=l"(r) : "f"(lo), "f"(hi)); return r;
}
static __device__ __forceinline__ void upk2(u64 v, float &lo, float &hi) {
    asm("mov.b64 {%0,%1}, %2;" : "=f"(lo), "=f"(hi) : "l"(v));
}
static __device__ __forceinline__ u64 f2add(u64 a, u64 b) {
    u64 r; asm("add.rn.f32x2 %0,%1,%2;" : "=l"(r) : "l"(a), "l"(b)); return r;
}
static __device__ __forceinline__ u64 f2mul(u64 a, u64 b) {
    u64 r; asm("mul.rn.f32x2 %0,%1,%2;" : "=l"(r) : "l"(a), "l"(b)); return r;
}
static __device__ __forceinline__ u64 f2fma(u64 a, u64 b, u64 c) {
    u64 r; asm("fma.rn.f32x2 %0,%1,%2,%3;" : "=l"(r) : "l"(a), "l"(b), "l"(c)); return r;
}
// ---- gpu-scope acquire/release flag ops ----
static __device__ __forceinline__ unsigned ld_acq(const unsigned* p) {
    unsigned v; asm volatile("ld.acquire.gpu.u32 %0,[%1];" : "=r"(v) : "l"(p) : "memory"); return v;
}
static __device__ __forceinline__ void st_rel(unsigned* p, unsigned v) {
    asm volatile("st.release.gpu.u32 [%0],%1;" :: "l"(p), "r"(v) : "memory");
}
// store two f32x2 pairs as one 16B smem write (STS.128)
static __device__ __forceinline__ void sts4(float* p, u64 a, u64 b) {
    float x, y, z, w; upk2(a, x, y); upk2(b, z, w);
    *(float4*)p = make_float4(x, y, z, w);
}

__global__ __launch_bounds__(NTH, 2) void mm_persist_kernel(
    const float* __restrict__ sig,        // (NSIG, TSTEPS, 3)
    const float* __restrict__ Bext,       // (1,3,NX,NY)
    const float* __restrict__ Msat_p,     // scalar
    const int*   __restrict__ src_pos,    // (3,2)
    const int*   __restrict__ probe_pos,  // (5,2)
    float*       __restrict__ out)        // (NSIG, TSTEPS, 5)
{
    __shared__ __align__(16) float stg[2][3][SROWS*EPP];

    const int tid = threadIdx.x;
    const int bid = blockIdx.x;
    const int s    = bid / NBS;
    const int tile = bid % NBS;
    const int tx   = tile / TILES_Y;
    const int ty   = tile % TILES_Y;
    const int ti0  = tx * TR;
    const int tj0  = ty * TC;

    unsigned* myflag = &g_done[bid*8];
    const unsigned base = ld_acq(myflag);   // monotonic across graph replays

    // zero smem once (guard-ring hygiene)
    for (int i = tid; i < 2*3*SROWS*EPP; i += NTH)
        ((float*)stg)[i] = 0.0f;

    const float Msat  = Msat_p[0];
    const float cexch = 7.0e-12f / ((Msat * 5e-8f) * 5e-8f);
    const float cdem  = 1.2566371e-06f * Msat;
    const float alpha = 0.01f;
    const float pref  = -1.0f / (1.0f + alpha*alpha);

    const u64 C_M4   = pk2(-4.0f, -4.0f);
    const u64 C_EXCH = pk2(cexch, cexch);
    const u64 C_NDEM = pk2(-cdem, -cdem);
    const u64 C_NEG1 = pk2(-1.0f, -1.0f);
    const u64 C_PREF = pk2(pref, pref);
    const u64 C_ALPH = pk2(alpha, alpha);
    const u64 C_SOT  = pk2(1.0e-4f, 1.0e-4f);
    const u64 C_TWO  = pk2(2.0f, 2.0f);
    const u64 C_CH   = pk2(0.439875f, 0.439875f);       // 0.5*h
    const u64 C_HH   = pk2(0.87975f, 0.87975f);         // h
    const u64 C_H6   = pk2((float)(0.87975/6.0), (float)(0.87975/6.0));

    const bool active = tid < NBLK;
    const int  br  = tid / BPR;          // 0..19
    const int  bc  = tid - br*BPR;       // 0..5
    const int  li0 = 2*br, lj0 = 4*bc;
    const int  gi0 = ti0 - 4 + li0;
    const int  gj0 = tj0 - 4 + lj0;
    // 2x4 blocks align with the 4-wide halo: fully in-grid or fully out per dim
    const bool ing = active && gi0 >= 0 && gi0 <= NXg-2 && gj0 >= 0 && gj0 <= NYg-4;
    const bool interior_blk = active && br >= 2 && br < 18 && bc >= 1 && bc < 5;
    const bool deep = br >= 4 && br < 16 && bc >= 2 && bc < 4;
    const bool band = interior_blk && !deep;
    const bool rim  = active && ing && !interior_blk;

    // rim block -> owning neighbor tile flag
    const unsigned* nflag = myflag;
    if (rim) {
        int drow = (br < 2) ? -1 : (br >= 18 ? 1 : 0);
        int dcol = (bc < 1) ? -1 : (bc >= 5 ? 1 : 0);
        int ntx = tx + drow, nty = ty + dcol;
        nflag = &g_done[((s*TILES_X + ntx)*TILES_Y + nty)*8];
    }

    const int  B0  = (ROW0 + li0)*EPP + (COL0 + lj0);   // 16B-aligned (COL0+lj0 % 4 == 0)
    const bool clU = (gi0 == 0), clD = (gi0+1 == NXg-1);
    const bool clL = (gj0 == 0), clR = (gj0+3 == NYg-1);
    const int  iU  = clU ? B0 : B0 - EPP;          // row above, 4 cols (LDS.128)
    const int  iD  = clD ? B0 + EPP : B0 + 2*EPP;  // row below, 4 cols (LDS.128)
    const int  iLt = clL ? B0 : B0 - 1;            // left of col0, row0 (row1 at +EPP)
    const int  iRt = clR ? B0 + 3 : B0 + 4;        // right of col3, row0
    const int  g0  = gi0*NYg + gj0;

    // packed state: 4 pairs per field: 0=(r0,c0c1) 1=(r0,c2c3) 2=(r1,c0c1) 3=(r1,c2c3)
    u64 MR[3][4], M[3][4], A[3][4];
    u64 BFX[4], BFY[4], BZ[4], BZT[4];
    #pragma unroll
    for (int p = 0; p < 4; p++) {
        MR[0][p] = 0; MR[1][p] = pk2(1.0f, 1.0f); MR[2][p] = 0;
        BFX[p] = 0; BFY[p] = 0; BZ[p] = 0;
    }
    int srcf = 0, prf = 0;   // 4 bits per cell, cell c = row*4 + col (8 cells)

    if (ing) {
        int sp[6], pp[10];
        #pragma unroll
        for (int k = 0; k < 6; k++)  sp[k] = src_pos[k];
        #pragma unroll
        for (int k = 0; k < 10; k++) pp[k] = probe_pos[k];
        #pragma unroll
        for (int X = 0; X < 3; X++) {
            float4 v0 = *(const float4*)&Bext[X*NCELL + g0];
            float4 v1 = *(const float4*)&Bext[X*NCELL + g0 + NYg];
            u64* dst = (X == 0) ? BFX : (X == 1) ? BFY : BZ;
            dst[0] = pk2(v0.x, v0.y); dst[1] = pk2(v0.z, v0.w);
            dst[2] = pk2(v1.x, v1.y); dst[3] = pk2(v1.z, v1.w);
        }
        #pragma unroll
        for (int c = 0; c < 8; c++) {
            int gi = gi0 + (c >> 2), gj = gj0 + (c & 3);
            #pragma unroll
            for (int k = 0; k < 3; k++)
                if (gi == sp[2*k] && gj == sp[2*k+1]) srcf |= (k+1) << (4*c);
            #pragma unroll
            for (int p = 0; p < 5; p++)
                if (gi == pp[2*p] && gj == pp[2*p+1]) prf |= (p+1) << (4*c);
        }
    }

    // initial stg[0] fill (t=0 stage field)
    if (active) {
        #pragma unroll
        for (int X = 0; X < 3; X++) {
            sts4(&stg[0][X][B0],     MR[X][0], MR[X][1]);
            sts4(&stg[0][X][B0+EPP], MR[X][2], MR[X][3]);
        }
    }

    for (int t = 0; t < TSTEPS; t++) {
        const float* __restrict__ bin  = g_state[t & 1][s];
        float*       __restrict__ bout = g_state[(t & 1) ^ 1][s];

        // rim: wait for owning neighbor to finish step t-1, then pull its band (L2)
        if (rim && t > 0) {
            unsigned tgt = base + (unsigned)t;
            while ((int)(ld_acq(nflag) - tgt) < 0) { }
            #pragma unroll
            for (int X = 0; X < 3; X++) {
                float4 v0 = __ldcg((const float4*)&bin[X*NCELL + g0]);
                float4 v1 = __ldcg((const float4*)&bin[X*NCELL + g0 + NYg]);
                MR[X][0] = pk2(v0.x, v0.y); MR[X][1] = pk2(v0.z, v0.w);
                MR[X][2] = pk2(v1.x, v1.y); MR[X][3] = pk2(v1.z, v1.w);
                sts4(&stg[0][X][B0],     MR[X][0], MR[X][1]);
                sts4(&stg[0][X][B0+EPP], MR[X][2], MR[X][3]);
            }
        }

        if (active) {
            if (srcf) {
                const float* sgp = &sig[(s*TSTEPS + t)*3];
                float sa[8];
                #pragma unroll
                for (int c = 0; c < 8; c++) {
                    int k = (srcf >> (4*c)) & 15;
                    sa[c] = k ? __ldg(&sgp[k-1]) : 0.0f;
                }
                BZT[0] = f2add(BZ[0], pk2(sa[0], sa[1]));
                BZT[1] = f2add(BZ[1], pk2(sa[2], sa[3]));
                BZT[2] = f2add(BZ[2], pk2(sa[4], sa[5]));
                BZT[3] = f2add(BZ[3], pk2(sa[6], sa[7]));
            } else {
                #pragma unroll
                for (int p = 0; p < 4; p++) BZT[p] = BZ[p];
            }
            #pragma unroll
            for (int X = 0; X < 3; X++)
                #pragma unroll
                for (int p = 0; p < 4; p++) { M[X][p] = MR[X][p]; A[X][p] = 0; }
        }
        __syncthreads();

        // One RK4 stage for all blocks (guard-ring garbage never reaches interior).
#define MM_STAGE(CUR, NXT, WISONE, DO_NEXT, C2)                                     \
        if (active) {                                                               \
            u64 LAP[3][4];                                                          \
            _Pragma("unroll")                                                       \
            for (int X = 0; X < 3; X++) {                                           \
                const float* Sp = stg[CUR][X];                                      \
                float4 U = *(const float4*)&Sp[iU];                                 \
                float4 D = *(const float4*)&Sp[iD];                                 \
                float lt0 = Sp[iLt], lt1 = Sp[iLt+EPP];                             \
                float rt0 = Sp[iRt], rt1 = Sp[iRt+EPP];                             \
                float a0,a1,a2,a3,b0,b1,b2,b3;                                      \
                upk2(M[X][0],a0,a1); upk2(M[X][1],a2,a3);                           \
                upk2(M[X][2],b0,b1); upk2(M[X][3],b2,b3);                           \
                u64 h00 = f2add(pk2(lt0,a0), pk2(a1,a2));                           \
                u64 h01 = f2add(pk2(a1,a2), pk2(a3,rt0));                           \
                u64 h10 = f2add(pk2(lt1,b0), pk2(b1,b2));                           \
                u64 h11 = f2add(pk2(b1,b2), pk2(b3,rt1));                           \
                LAP[X][0] = f2fma(M[X][0], C_M4, f2add(h00, f2add(pk2(U.x,U.y), M[X][2]))); \
                LAP[X][1] = f2fma(M[X][1], C_M4, f2add(h01, f2add(pk2(U.z,U.w), M[X][3]))); \
                LAP[X][2] = f2fma(M[X][2], C_M4, f2add(h10, f2add(M[X][0], pk2(D.x,D.y)))); \
                LAP[X][3] = f2fma(M[X][3], C_M4, f2add(h11, f2add(M[X][1], pk2(D.z,D.w)))); \
            }                                                                       \
            _Pragma("unroll")                                                       \
            for (int p = 0; p < 4; p++) {                                           \
                u64 bx = f2fma(LAP[0][p], C_EXCH, BFX[p]);                          \
                u64 by = f2fma(LAP[1][p], C_EXCH, BFY[p]);                          \
                u64 bz = f2fma(M[2][p], C_NDEM, f2fma(LAP[2][p], C_EXCH, BZT[p]));  \
                u64 n0 = f2mul(M[0][p], C_NEG1);                                    \
                u64 n1 = f2mul(M[1][p], C_NEG1);                                    \
                u64 n2 = f2mul(M[2][p], C_NEG1);                                    \
                u64 cx = f2fma(M[1][p], bz, f2mul(n2, by));                         \
                u64 cy = f2fma(M[2][p], bx, f2mul(n0, bz));                         \
                u64 cz = f2fma(M[0][p], by, f2mul(n1, bx));                         \
                u64 dx = f2fma(M[1][p], cz, f2mul(n2, cy));                         \
                u64 dy = f2fma(M[2][p], cx, f2mul(n0, cz));                         \
                u64 dz = f2fma(M[0][p], cy, f2mul(n1, cx));                         \
                u64 kx = f2fma(C_SOT, f2mul(M[1][p], M[0][p]),                      \
                               f2mul(C_PREF, f2fma(C_ALPH, dx, cx)));               \
                u64 ky = f2fma(C_SOT, f2fma(n0, M[0][p], f2mul(n2, M[2][p])),       \
                               f2mul(C_PREF, f2fma(C_ALPH, dy, cy)));               \
                u64 kz = f2fma(C_SOT, f2mul(M[1][p], M[2][p]),                      \
                               f2mul(C_PREF, f2fma(C_ALPH, dz, cz)));               \
                if (WISONE) {                                                       \
                    A[0][p] = f2add(A[0][p], kx);                                   \
                    A[1][p] = f2add(A[1][p], ky);                                   \
                    A[2][p] = f2add(A[2][p], kz);                                   \
                } else {                                                            \
                    A[0][p] = f2fma(kx, C_TWO, A[0][p]);                            \
                    A[1][p] = f2fma(ky, C_TWO, A[1][p]);                            \
                    A[2][p] = f2fma(kz, C_TWO, A[2][p]);                            \
                }                                                                   \
                if (DO_NEXT) {                                                      \
                    M[0][p] = f2fma(kx, C2, MR[0][p]);                              \
                    M[1][p] = f2fma(ky, C2, MR[1][p]);                              \
                    M[2][p] = f2fma(kz, C2, MR[2][p]);                              \
                }                                                                   \
            }                                                                       \
            if (DO_NEXT) {                                                          \
                _Pragma("unroll")                                                   \
                for (int X = 0; X < 3; X++) {                                       \
                    sts4(&stg[NXT][X][B0],     M[X][0], M[X][1]);                   \
                    sts4(&stg[NXT][X][B0+EPP], M[X][2], M[X][3]);                   \
                }                                                                   \
            }                                                                       \
        }                                                                           \
        if (DO_NEXT) __syncthreads();

        MM_STAGE(0, 1, true,  true,  C_CH)   // k1 -> m + 0.5h k1
        MM_STAGE(1, 0, false, true,  C_CH)   // k2 -> m + 0.5h k2
        MM_STAGE(0, 1, false, true,  C_HH)   // k3 -> m + h   k3
        MM_STAGE(1, 0, true,  false, C_CH)   // k4 (reads stg[1] only; no sync)
#undef MM_STAGE

        // combine; interior stays in regs; stg[0] pre-filled for next step
        if (interior_blk) {
            #pragma unroll
            for (int X = 0; X < 3; X++) {
                #pragma unroll
                for (int p = 0; p < 4; p++)
                    MR[X][p] = f2fma(A[X][p], C_H6, MR[X][p]);
                sts4(&stg[0][X][B0],     MR[X][0], MR[X][1]);
                sts4(&stg[0][X][B0+EPP], MR[X][2], MR[X][3]);
            }
            if (band) {
                #pragma unroll
                for (int X = 0; X < 3; X++) {
                    float x0,y0,z0,w0,x1,y1,z1,w1;
                    upk2(MR[X][0],x0,y0); upk2(MR[X][1],z0,w0);
                    upk2(MR[X][2],x1,y1); upk2(MR[X][3],z1,w1);
                    __stcg((float4*)&bout[X*NCELL + g0],       make_float4(x0,y0,z0,w0));
                    __stcg((float4*)&bout[X*NCELL + g0 + NYg], make_float4(x1,y1,z1,w1));
                }
            }
            if (prf) {
                float zz[8];
                upk2(MR[2][0], zz[0], zz[1]); upk2(MR[2][1], zz[2], zz[3]);
                upk2(MR[2][2], zz[4], zz[5]); upk2(MR[2][3], zz[6], zz[7]);
                #pragma unroll
                for (int c = 0; c < 8; c++) {
                    int p = (prf >> (4*c)) & 15;
                    if (p) out[(s*TSTEPS + t)*5 + (p-1)] = zz[c];
                }
            }
        }

        // post completion of step t (release after band stores)
        __syncthreads();
        if (tid == 0) {
            __threadfence();
            st_rel(myflag, base + (unsigned)(t + 1));
        }
    }
}

extern "C" void kernel_launch(void* const* d_in, const int* in_sizes, int n_in,
                              void* d_out, int out_size) {
    const float* sig       = (const float*)d_in[0];  // (2,256,3)
    const float* Bext      = (const float*)d_in[1];  // (1,3,256,256)
    const float* Msat      = (const float*)d_in[2];  // scalar
    const int*   src_pos   = (const int*)d_in[3];    // (3,2)
    const int*   probe_pos = (const int*)d_in[4];    // (5,2)
    float*       out       = (float*)d_out;          // (2,256,5)

    mm_persist_kernel<<<NB, NTH>>>(sig, Bext, Msat, src_pos, probe_pos, out);
}